// round 13
// baseline (speedup 1.0000x reference)
#include <cuda_runtime.h>

#define Bn 32
#define Tn 128
#define In 256
#define Hn 256
#define IH 512
#define On 128
#define NBLK 256      // persistent blocks; 64 KB smem, <=128 regs => 2 blocks/SM
#define NTHR 256      // 8 warps

typedef unsigned long long ull;

__device__ float g_h[2][Bn * Hn];                     // ping-pong hidden state
__device__ __align__(128) unsigned g_cnt[Bn][32];     // per-BATCH counters, 128B apart

// ---------------------------------------------------------------------------
__global__ void init_kernel()
{
    int i = blockIdx.x * blockDim.x + threadIdx.x;
    if (i < Bn) g_cnt[i][0] = 0u;
    for (int k = i; k < Bn * Hn; k += gridDim.x * blockDim.x) g_h[0][k] = 0.f;
}

// ---------------------------------------------------------------------------
__device__ __forceinline__ float warp_sum(float v)
{
#pragma unroll
    for (int o = 16; o > 0; o >>= 1) v += __shfl_xor_sync(0xffffffffu, v, o);
    return v;
}
__device__ __forceinline__ float tanh_fast(float v)
{
    float r; asm("tanh.approx.f32 %0, %1;" : "=f"(r) : "f"(v)); return r;
}
__device__ __forceinline__ unsigned ld_acquire(const unsigned* p)
{
    unsigned v;
    asm volatile("ld.acquire.gpu.global.u32 %0, [%1];" : "=r"(v) : "l"(p) : "memory");
    return v;
}
__device__ __forceinline__ void red_release(unsigned* p)
{
    asm volatile("red.release.gpu.global.add.u32 [%0], 1;" :: "l"(p) : "memory");
}
// ---- packed f32x2 primitives ----
__device__ __forceinline__ ull f2_add(ull a, ull b)
{ ull d; asm("add.rn.f32x2 %0, %1, %2;" : "=l"(d) : "l"(a), "l"(b)); return d; }
__device__ __forceinline__ ull f2_mul(ull a, ull b)
{ ull d; asm("mul.rn.f32x2 %0, %1, %2;" : "=l"(d) : "l"(a), "l"(b)); return d; }
__device__ __forceinline__ ull f2_fma(ull a, ull b, ull c)
{ ull d; asm("fma.rn.f32x2 %0, %1, %2, %3;" : "=l"(d) : "l"(a), "l"(b), "l"(c)); return d; }
__device__ __forceinline__ ull f2_bcast(float v)
{ ull d; asm("mov.b64 %0, {%1, %1};" : "=l"(d) : "f"(v)); return d; }
__device__ __forceinline__ float f2_fold(ull v)
{ float lo, hi; asm("mov.b64 {%0, %1}, %2;" : "=f"(lo), "=f"(hi) : "l"(v)); return lo + hi; }
__device__ __forceinline__ ulonglong2 ldnc2(const ulonglong2* p)
{ ulonglong2 v; asm("ld.global.nc.v2.u64 {%0,%1}, [%2];" : "=l"(v.x), "=l"(v.y) : "l"(p)); return v; }
__device__ __forceinline__ ulonglong2 ldcg2(const ulonglong2* p)
{ ulonglong2 v; asm volatile("ld.global.cg.v2.u64 {%0,%1}, [%2];" : "=l"(v.x), "=l"(v.y) : "l"(p)); return v; }

// ---------------------------------------------------------------------------
// Persistent kernel, 2 blocks/SM. Block owns h-row bid x 32 batches; F slice
// (32 rows x 512 = 64 KB) in smem. Warp w handles batches w + {0,8,16,24}.
//
// DATAFLOW SYNC (no bar.sync in the loop): per-batch counters. A warp
// arrives on g_cnt[bi] right after storing h[bi] (release orders the STG);
// before B1 it waits only on ITS 4 batch counters (lane-0 acquire poll +
// __syncwarp fence). Batches/warps/blocks drift freely — no global
// rendezvous, no straggler coupling across batches.
// ---------------------------------------------------------------------------
__global__ __launch_bounds__(NTHR, 2) void persist_kernel(
    const float* __restrict__ x,
    const float* __restrict__ Wl,
    const float* __restrict__ Wg,
    const float* __restrict__ W,
    const float* __restrict__ bias,
    const float* __restrict__ Wout,
    const float* __restrict__ bout,
    float* __restrict__ out)
{
    extern __shared__ float F_sm[];                    // 64 KB
    ulonglong2* __restrict__ F2 = (ulonglong2*)F_sm;   // [32][128] 16B units

    const int tid  = threadIdx.x;
    const int wid  = tid >> 5, lane = tid & 31;
    const int bi0  = wid;                      // 0..7
    const int h    = blockIdx.x;

    // Pin this block's weight-row slices (pair domain).
    ulonglong2 w2[4], l2[4], g2[4];
    {
        const ulonglong2* Wp = (const ulonglong2*)(W  + (size_t)h * IH);
        const ulonglong2* Lp = (const ulonglong2*)(Wl + (size_t)h * IH);
        const ulonglong2* Gp = (const ulonglong2*)(Wg + (size_t)h * IH);
#pragma unroll
        for (int k = 0; k < 4; k++) {
            int f4 = k * 32 + lane;
            w2[k] = ldnc2(Wp + f4);
            l2[k] = ldnc2(Lp + f4);
            g2[k] = ldnc2(Gp + f4);
        }
    }
    const float bia = __ldg(bias + h);

    // Zero this warp's F rows (warp-private).
    {
        ulonglong2 z; z.x = 0ull; z.y = 0ull;
#pragma unroll
        for (int u = 0; u < 4; u++) {
            ulonglong2* Fr = F2 + (bi0 + u * 8) * (IH / 4);
#pragma unroll
            for (int k = 0; k < 4; k++) Fr[k * 32 + lane] = z;
        }
    }

    // Bootstrap partials for t=0 (F=0 => tw=W).
    float ssp[4], rn[4], hn[4], ssh[4];
    ull dxp[4];
    {
        ull sw = f2_mul(w2[0].x, w2[0].x);
        sw = f2_fma(w2[0].y, w2[0].y, sw);
        sw = f2_fma(w2[1].x, w2[1].x, sw);
        sw = f2_fma(w2[1].y, w2[1].y, sw);
        sw = f2_fma(w2[2].x, w2[2].x, sw);
        sw = f2_fma(w2[2].y, w2[2].y, sw);
        sw = f2_fma(w2[3].x, w2[3].x, sw);
        sw = f2_fma(w2[3].y, w2[3].y, sw);
        const float ssw = f2_fold(sw);
#pragma unroll
        for (int u = 0; u < 4; u++) {
            const int bi = bi0 + u * 8;
            const ulonglong2* xr = (const ulonglong2*)(x + (size_t)bi * Tn * In);
            ulonglong2 xv0 = ldnc2(xr + lane);
            ulonglong2 xv1 = ldnc2(xr + 32 + lane);
            ull a = f2_mul(xv0.x, w2[0].x);
            a = f2_fma(xv0.y, w2[0].y, a);
            a = f2_fma(xv1.x, w2[1].x, a);
            a = f2_fma(xv1.y, w2[1].y, a);
            ssp[u] = ssw;
            dxp[u] = a;
        }
    }

    for (int t = 0; t < Tn; t++) {
        const ulonglong2* __restrict__ hin = (const ulonglong2*)g_h[t & 1];
        float* __restrict__ hout = g_h[(t & 1) ^ 1];
        const int tn = (t + 1 < Tn) ? t + 1 : t;

        // ss reduce + rsqrt (4 interleaved chains).
#pragma unroll
        for (int o = 16; o > 0; o >>= 1) {
            ssp[0] += __shfl_xor_sync(0xffffffffu, ssp[0], o);
            ssp[1] += __shfl_xor_sync(0xffffffffu, ssp[1], o);
            ssp[2] += __shfl_xor_sync(0xffffffffu, ssp[2], o);
            ssp[3] += __shfl_xor_sync(0xffffffffu, ssp[3], o);
        }
#pragma unroll
        for (int u = 0; u < 4; u++) rn[u] = rsqrtf(ssp[u]);

        // ---------- warp-autonomous wait: only THIS warp's 4 batches ----------
        if (t > 0 && lane == 0) {
            const unsigned target = (unsigned)NBLK * (unsigned)t;
            for (;;) {
                unsigned c0 = ld_acquire(&g_cnt[bi0][0]);
                unsigned c1 = ld_acquire(&g_cnt[bi0 + 8][0]);
                unsigned c2 = ld_acquire(&g_cnt[bi0 + 16][0]);
                unsigned c3 = ld_acquire(&g_cnt[bi0 + 24][0]);
                if (c0 >= target && c1 >= target && c2 >= target && c3 >= target)
                    break;
                __nanosleep(64);
            }
        }
        __syncwarp();   // fence: counter acquire (lane 0) -> all lanes' h loads

        // ---------- B1: dot -> publish h + arrive -> fused h-part writeback ----------
        ulonglong2 ha[4], hb[4];
#pragma unroll
        for (int u = 0; u < 4; u++) {          // 8 LDGs up front (MLP)
            const int bi = bi0 + u * 8;
            ha[u] = ldcg2(hin + bi * (Hn / 16) * 4 + lane);
            hb[u] = ldcg2(hin + bi * (Hn / 16) * 4 + 32 + lane);
        }
#pragma unroll
        for (int u = 0; u < 4; u++) {
            const int bi = bi0 + u * 8;
            ulonglong2* __restrict__ Fr = F2 + bi * (IH / 4);
            ulonglong2 Fv2 = Fr[64 + lane], Fv3 = Fr[96 + lane];
            ull t2x = f2_add(w2[2].x, Fv2.x), t2y = f2_add(w2[2].y, Fv2.y);
            ull t3x = f2_add(w2[3].x, Fv3.x), t3y = f2_add(w2[3].y, Fv3.y);
            ull acc = dxp[u];
            acc = f2_fma(ha[u].x, t2x, acc);
            acc = f2_fma(ha[u].y, t2y, acc);
            acc = f2_fma(hb[u].x, t3x, acc);
            acc = f2_fma(hb[u].y, t3y, acc);
            float tot = warp_sum(f2_fold(acc));
            const float hv = tanh_fast(tot + bia) * rn[u];
            hn[u] = hv;
            if (lane == 0) {
                hout[bi * Hn + h] = hv;
                red_release(&g_cnt[bi][0]);    // arrive: orders the STG above
            }

            // fused h-part writeback (Fv2/3, ha/hb still live)
            const ull rr2 = f2_bcast(rn[u]);
            const ull hv2 = f2_bcast(hv);
            ulonglong2 n2, n3;
            n2.x = f2_fma(g2[2].x, f2_mul(ha[u].x, hv2), f2_mul(l2[2].x, f2_mul(Fv2.x, rr2)));
            n2.y = f2_fma(g2[2].y, f2_mul(ha[u].y, hv2), f2_mul(l2[2].y, f2_mul(Fv2.y, rr2)));
            n3.x = f2_fma(g2[3].x, f2_mul(hb[u].x, hv2), f2_mul(l2[3].x, f2_mul(Fv3.x, rr2)));
            n3.y = f2_fma(g2[3].y, f2_mul(hb[u].y, hv2), f2_mul(l2[3].y, f2_mul(Fv3.y, rr2)));
            Fr[64 + lane] = n2;
            Fr[96 + lane] = n3;

            // h-part contribution to next-step ss (tw23_next = w + n)
            ull u2x = f2_add(w2[2].x, n2.x), u2y = f2_add(w2[2].y, n2.y);
            ull u3x = f2_add(w2[3].x, n3.x), u3y = f2_add(w2[3].y, n3.y);
            ull sh = f2_mul(u2x, u2x);
            sh = f2_fma(u2y, u2y, sh);
            sh = f2_fma(u3x, u3x, sh);
            sh = f2_fma(u3y, u3y, sh);
            ssh[u] = f2_fold(sh);
        }

        // ---------- B2: x-part writeback + next-step partials ----------
#pragma unroll
        for (int u = 0; u < 4; u++) {
            const int bi = bi0 + u * 8;
            ulonglong2* __restrict__ Fr = F2 + bi * (IH / 4);
            const ull rr2 = f2_bcast(rn[u]);
            const ull hv2 = f2_bcast(hn[u]);

            const ulonglong2* __restrict__ xr =
                (const ulonglong2*)(x + ((size_t)bi * Tn + t) * In);
            ulonglong2 xv0 = ldnc2(xr + lane);          // L1 hits
            ulonglong2 xv1 = ldnc2(xr + 32 + lane);
            ulonglong2 Fv0 = Fr[lane], Fv1 = Fr[32 + lane];

            ulonglong2 n0, n1;
            n0.x = f2_fma(g2[0].x, f2_mul(xv0.x, hv2), f2_mul(l2[0].x, f2_mul(Fv0.x, rr2)));
            n0.y = f2_fma(g2[0].y, f2_mul(xv0.y, hv2), f2_mul(l2[0].y, f2_mul(Fv0.y, rr2)));
            n1.x = f2_fma(g2[1].x, f2_mul(xv1.x, hv2), f2_mul(l2[1].x, f2_mul(Fv1.x, rr2)));
            n1.y = f2_fma(g2[1].y, f2_mul(xv1.y, hv2), f2_mul(l2[1].y, f2_mul(Fv1.y, rr2)));
            Fr[lane] = n0;
            Fr[32 + lane] = n1;

            ull t0x = f2_add(w2[0].x, n0.x), t0y = f2_add(w2[0].y, n0.y);
            ull t1x = f2_add(w2[1].x, n1.x), t1y = f2_add(w2[1].y, n1.y);

            ull ss = f2_mul(t0x, t0x);
            ss = f2_fma(t0y, t0y, ss);
            ss = f2_fma(t1x, t1x, ss);
            ss = f2_fma(t1y, t1y, ss);
            ssp[u] = f2_fold(ss) + ssh[u];

            const ulonglong2* __restrict__ xq =
                (const ulonglong2*)(x + ((size_t)bi * Tn + tn) * In);
            ulonglong2 xa = ldnc2(xq + lane);
            ulonglong2 xb = ldnc2(xq + 32 + lane);
            ull dx = f2_mul(xa.x, t0x);
            dx = f2_fma(xa.y, t0y, dx);
            dx = f2_fma(xb.x, t1x, dx);
            dx = f2_fma(xb.y, t1y, dx);
            dxp[u] = dx;
        }
    }

    // ---- F writeout (warp-private rows; no sync needed) ----
    float* __restrict__ Fout = out + Bn * On + Bn * Hn;
    ulonglong2* __restrict__ Fo2 = (ulonglong2*)Fout;
#pragma unroll
    for (int u = 0; u < 4; u++) {
        const int bb = bi0 + u * 8;
        const int grow = bb * Hn + h;
        const ulonglong2* Fr = F2 + bb * (IH / 4);
#pragma unroll
        for (int k = 0; k < 4; k++) {
            int f4 = k * 32 + lane;
            Fo2[(size_t)grow * (IH / 4) + f4] = Fr[f4];
        }
    }

    // ---- epilogue: needs all batches' final h ----
    if (blockIdx.x < 64) {
        if (tid == 0) {
            const unsigned target = (unsigned)NBLK * (unsigned)Tn;
            for (int b = 0; b < Bn; b++)
                while (ld_acquire(&g_cnt[b][0]) < target) __nanosleep(64);
        }
        __syncthreads();
    }

    if (blockIdx.x < 32) {
        const int b = blockIdx.x;
        for (int i = tid; i < Hn; i += NTHR)
            F_sm[i] = __ldcg(&g_h[0][b * Hn + i]);   // T even -> final h in buf 0
        __syncthreads();
        const float4* hv4 = (const float4*)F_sm;
        for (int o = wid; o < On; o += 8) {
            const float4* wr = (const float4*)(Wout + (size_t)o * Hn);
            float acc = 0.f;
#pragma unroll
            for (int k = 0; k < 2; k++) {
                int j4 = k * 32 + lane;
                float4 w = __ldg(wr + j4);
                float4 hv = hv4[j4];
                acc += w.x * hv.x + w.y * hv.y + w.z * hv.z + w.w * hv.w;
            }
            acc = warp_sum(acc);
            if (lane == 0) out[b * On + o] = acc + __ldg(bout + o);
        }
    } else if (blockIdx.x < 64) {
        const int b = blockIdx.x - 32;
        for (int i = tid; i < Hn; i += NTHR)
            out[Bn * On + b * Hn + i] = __ldcg(&g_h[0][b * Hn + i]);
    }
}

// ---------------------------------------------------------------------------
extern "C" void kernel_launch(void* const* d_in, const int* in_sizes, int n_in,
                              void* d_out, int out_size)
{
    const float* sentence = (const float*)d_in[0];
    const float* Wl   = (const float*)d_in[1];
    const float* Wg   = (const float*)d_in[2];
    const float* W    = (const float*)d_in[3];
    const float* bias = (const float*)d_in[4];
    const float* Wout = (const float*)d_in[5];
    const float* bout = (const float*)d_in[6];
    float* out = (float*)d_out;

    const int smem = 32 * IH * sizeof(float);  // 65536
    cudaFuncSetAttribute(persist_kernel, cudaFuncAttributeMaxDynamicSharedMemorySize, smem);

    init_kernel<<<32, 256>>>();
    persist_kernel<<<NBLK, NTHR, smem>>>(sentence, Wl, Wg, W, bias, Wout, bout, out);
}

// round 14
// speedup vs baseline: 1.0019x; 1.0019x over previous
#include <cuda_runtime.h>

#define Bn 32
#define Tn 128
#define In 256
#define Hn 256
#define IH 512
#define On 128
#define NBLK 256      // persistent blocks; 64 KB smem, <=128 regs => 2 blocks/SM
#define NTHR 256      // 8 warps
#define NLINES 8      // distributed arrival-counter lines

typedef unsigned long long ull;

__device__ float g_h[2][Bn * Hn];                        // ping-pong hidden state
__device__ __align__(128) unsigned g_bar8[NLINES][32];   // arrival lines, 128B apart

// ---------------------------------------------------------------------------
__global__ void init_kernel()
{
    int i = blockIdx.x * blockDim.x + threadIdx.x;
    if (i < NLINES) g_bar8[i][0] = 0u;
    for (int k = i; k < Bn * Hn; k += gridDim.x * blockDim.x) g_h[0][k] = 0.f;
}

// ---------------------------------------------------------------------------
__device__ __forceinline__ float warp_sum(float v)
{
#pragma unroll
    for (int o = 16; o > 0; o >>= 1) v += __shfl_xor_sync(0xffffffffu, v, o);
    return v;
}
__device__ __forceinline__ float tanh_fast(float v)
{
    float r; asm("tanh.approx.f32 %0, %1;" : "=f"(r) : "f"(v)); return r;
}
__device__ __forceinline__ unsigned ld_acquire(const unsigned* p)
{
    unsigned v;
    asm volatile("ld.acquire.gpu.global.u32 %0, [%1];" : "=r"(v) : "l"(p) : "memory");
    return v;
}
__device__ __forceinline__ void red_release(unsigned* p)
{
    asm volatile("red.release.gpu.global.add.u32 [%0], 1;" :: "l"(p) : "memory");
}
__device__ __forceinline__ unsigned atom_inc_cta_shared(unsigned* p)
{
    unsigned old;
    unsigned addr = (unsigned)__cvta_generic_to_shared(p);
    asm volatile("atom.acq_rel.cta.shared.add.u32 %0, [%1], 1;"
                 : "=r"(old) : "r"(addr) : "memory");
    return old;
}
// ---- packed f32x2 primitives ----
__device__ __forceinline__ ull f2_add(ull a, ull b)
{ ull d; asm("add.rn.f32x2 %0, %1, %2;" : "=l"(d) : "l"(a), "l"(b)); return d; }
__device__ __forceinline__ ull f2_mul(ull a, ull b)
{ ull d; asm("mul.rn.f32x2 %0, %1, %2;" : "=l"(d) : "l"(a), "l"(b)); return d; }
__device__ __forceinline__ ull f2_fma(ull a, ull b, ull c)
{ ull d; asm("fma.rn.f32x2 %0, %1, %2, %3;" : "=l"(d) : "l"(a), "l"(b), "l"(c)); return d; }
__device__ __forceinline__ ull f2_bcast(float v)
{ ull d; asm("mov.b64 %0, {%1, %1};" : "=l"(d) : "f"(v)); return d; }
__device__ __forceinline__ float f2_fold(ull v)
{ float lo, hi; asm("mov.b64 {%0, %1}, %2;" : "=f"(lo), "=f"(hi) : "l"(v)); return lo + hi; }
__device__ __forceinline__ ulonglong2 ldnc2(const ulonglong2* p)
{ ulonglong2 v; asm("ld.global.nc.v2.u64 {%0,%1}, [%2];" : "=l"(v.x), "=l"(v.y) : "l"(p)); return v; }
__device__ __forceinline__ ulonglong2 ldcg2(const ulonglong2* p)
{ ulonglong2 v; asm volatile("ld.global.cg.v2.u64 {%0,%1}, [%2];" : "=l"(v.x), "=l"(v.y) : "l"(p)); return v; }

// Leader wait: all NLINES arrival lines >= target (target = (NBLK/NLINES)*t).
__device__ __forceinline__ void leader_wait(unsigned target)
{
    for (;;) {
        unsigned c0 = ld_acquire(&g_bar8[0][0]);
        unsigned c1 = ld_acquire(&g_bar8[1][0]);
        unsigned c2 = ld_acquire(&g_bar8[2][0]);
        unsigned c3 = ld_acquire(&g_bar8[3][0]);
        unsigned c4 = ld_acquire(&g_bar8[4][0]);
        unsigned c5 = ld_acquire(&g_bar8[5][0]);
        unsigned c6 = ld_acquire(&g_bar8[6][0]);
        unsigned c7 = ld_acquire(&g_bar8[7][0]);
        if (c0 >= target && c1 >= target && c2 >= target && c3 >= target &&
            c4 >= target && c5 >= target && c6 >= target && c7 >= target)
            break;
    }
}

// ---------------------------------------------------------------------------
// Persistent kernel, 2 blocks/SM (R12 compute core; distributed-line barrier).
// Block owns h-row bid x 32 batches; F slice (32 rows x 512 = 64 KB) in smem.
// Warp w handles batches w + {0,8,16,24}; lane slice: 16B unit k*32+lane.
//
// Step: [reduce ss->rn | leader 8-line poll + bar.sync |
//   B1 per batch: LDS Fv2/3 -> dot -> tanh -> STG h -> fused n2/n3 STS + ssh |
//   arrive (smem atom; 8th warp -> red on line bid&7) |
//   B2 per batch: x-part writeback + next-step ss/dx partials]
// ---------------------------------------------------------------------------
__global__ __launch_bounds__(NTHR, 2) void persist_kernel(
    const float* __restrict__ x,
    const float* __restrict__ Wl,
    const float* __restrict__ Wg,
    const float* __restrict__ W,
    const float* __restrict__ bias,
    const float* __restrict__ Wout,
    const float* __restrict__ bout,
    float* __restrict__ out)
{
    extern __shared__ float F_sm[];                    // 64 KB
    ulonglong2* __restrict__ F2 = (ulonglong2*)F_sm;   // [32][128] 16B units
    __shared__ unsigned s_cnt;

    const int tid  = threadIdx.x;
    const int wid  = tid >> 5, lane = tid & 31;
    const int bi0  = wid;                      // 0..7
    const int h    = blockIdx.x;

    if (tid == 0) s_cnt = 0u;

    // Pin this block's weight-row slices (pair domain).
    ulonglong2 w2[4], l2[4], g2[4];
    {
        const ulonglong2* Wp = (const ulonglong2*)(W  + (size_t)h * IH);
        const ulonglong2* Lp = (const ulonglong2*)(Wl + (size_t)h * IH);
        const ulonglong2* Gp = (const ulonglong2*)(Wg + (size_t)h * IH);
#pragma unroll
        for (int k = 0; k < 4; k++) {
            int f4 = k * 32 + lane;
            w2[k] = ldnc2(Wp + f4);
            l2[k] = ldnc2(Lp + f4);
            g2[k] = ldnc2(Gp + f4);
        }
    }
    const float bia = __ldg(bias + h);

    // Zero this warp's F rows.
    {
        ulonglong2 z; z.x = 0ull; z.y = 0ull;
#pragma unroll
        for (int u = 0; u < 4; u++) {
            ulonglong2* Fr = F2 + (bi0 + u * 8) * (IH / 4);
#pragma unroll
            for (int k = 0; k < 4; k++) Fr[k * 32 + lane] = z;
        }
    }

    // Bootstrap partials for t=0 (F=0 => tw=W).
    float ssp[4], rn[4], hn[4], ssh[4];
    ull dxp[4];
    {
        ull sw = f2_mul(w2[0].x, w2[0].x);
        sw = f2_fma(w2[0].y, w2[0].y, sw);
        sw = f2_fma(w2[1].x, w2[1].x, sw);
        sw = f2_fma(w2[1].y, w2[1].y, sw);
        sw = f2_fma(w2[2].x, w2[2].x, sw);
        sw = f2_fma(w2[2].y, w2[2].y, sw);
        sw = f2_fma(w2[3].x, w2[3].x, sw);
        sw = f2_fma(w2[3].y, w2[3].y, sw);
        const float ssw = f2_fold(sw);
#pragma unroll
        for (int u = 0; u < 4; u++) {
            const int bi = bi0 + u * 8;
            const ulonglong2* xr = (const ulonglong2*)(x + (size_t)bi * Tn * In);
            ulonglong2 xv0 = ldnc2(xr + lane);
            ulonglong2 xv1 = ldnc2(xr + 32 + lane);
            ull a = f2_mul(xv0.x, w2[0].x);
            a = f2_fma(xv0.y, w2[0].y, a);
            a = f2_fma(xv1.x, w2[1].x, a);
            a = f2_fma(xv1.y, w2[1].y, a);
            ssp[u] = ssw;
            dxp[u] = a;
        }
    }

    for (int t = 0; t < Tn; t++) {
        const ulonglong2* __restrict__ hin = (const ulonglong2*)g_h[t & 1];
        float* __restrict__ hout = g_h[(t & 1) ^ 1];
        const int tn = (t + 1 < Tn) ? t + 1 : t;

        // ss reduce + rsqrt (off critical path; 4 interleaved chains).
#pragma unroll
        for (int o = 16; o > 0; o >>= 1) {
            ssp[0] += __shfl_xor_sync(0xffffffffu, ssp[0], o);
            ssp[1] += __shfl_xor_sync(0xffffffffu, ssp[1], o);
            ssp[2] += __shfl_xor_sync(0xffffffffu, ssp[2], o);
            ssp[3] += __shfl_xor_sync(0xffffffffu, ssp[3], o);
        }
#pragma unroll
        for (int u = 0; u < 4; u++) rn[u] = rsqrtf(ssp[u]);

        // ---------- wait: h(t-1) published by all blocks ----------
        if (tid == 0) leader_wait((unsigned)(NBLK / NLINES) * (unsigned)t);
        __syncthreads();

        // ---------- B1: per batch, dot -> publish h -> fused h-part writeback ----------
        ulonglong2 ha[4], hb[4];
#pragma unroll
        for (int u = 0; u < 4; u++) {          // 8 LDGs up front (MLP)
            const int bi = bi0 + u * 8;
            ha[u] = ldcg2(hin + bi * (Hn / 16) * 4 + lane);
            hb[u] = ldcg2(hin + bi * (Hn / 16) * 4 + 32 + lane);
        }
#pragma unroll
        for (int u = 0; u < 4; u++) {
            const int bi = bi0 + u * 8;
            ulonglong2* __restrict__ Fr = F2 + bi * (IH / 4);
            ulonglong2 Fv2 = Fr[64 + lane], Fv3 = Fr[96 + lane];
            ull t2x = f2_add(w2[2].x, Fv2.x), t2y = f2_add(w2[2].y, Fv2.y);
            ull t3x = f2_add(w2[3].x, Fv3.x), t3y = f2_add(w2[3].y, Fv3.y);
            ull acc = dxp[u];
            acc = f2_fma(ha[u].x, t2x, acc);
            acc = f2_fma(ha[u].y, t2y, acc);
            acc = f2_fma(hb[u].x, t3x, acc);
            acc = f2_fma(hb[u].y, t3y, acc);
            float tot = warp_sum(f2_fold(acc));
            const float hv = tanh_fast(tot + bia) * rn[u];
            hn[u] = hv;
            if (lane == 0) hout[bi * Hn + h] = hv;

            // fused h-part writeback (Fv2/3, ha/hb still live — no reload)
            const ull rr2 = f2_bcast(rn[u]);
            const ull hv2 = f2_bcast(hv);
            ulonglong2 n2, n3;
            n2.x = f2_fma(g2[2].x, f2_mul(ha[u].x, hv2), f2_mul(l2[2].x, f2_mul(Fv2.x, rr2)));
            n2.y = f2_fma(g2[2].y, f2_mul(ha[u].y, hv2), f2_mul(l2[2].y, f2_mul(Fv2.y, rr2)));
            n3.x = f2_fma(g2[3].x, f2_mul(hb[u].x, hv2), f2_mul(l2[3].x, f2_mul(Fv3.x, rr2)));
            n3.y = f2_fma(g2[3].y, f2_mul(hb[u].y, hv2), f2_mul(l2[3].y, f2_mul(Fv3.y, rr2)));
            Fr[64 + lane] = n2;
            Fr[96 + lane] = n3;

            // h-part contribution to next-step ss (tw23_next = w + n)
            ull u2x = f2_add(w2[2].x, n2.x), u2y = f2_add(w2[2].y, n2.y);
            ull u3x = f2_add(w2[3].x, n3.x), u3y = f2_add(w2[3].y, n3.y);
            ull sh = f2_mul(u2x, u2x);
            sh = f2_fma(u2y, u2y, sh);
            sh = f2_fma(u3x, u3x, sh);
            sh = f2_fma(u3y, u3y, sh);
            ssh[u] = f2_fold(sh);
        }

        // ---------- arrive (smem acq_rel -> 1 red on line bid&7) ----------
        if (lane == 0) {
            unsigned old = atom_inc_cta_shared(&s_cnt);
            if ((old & 7u) == 7u) red_release(&g_bar8[blockIdx.x & (NLINES - 1)][0]);
        }

        // ---------- B2 (off critical path): x-part writeback + partials ----------
#pragma unroll
        for (int u = 0; u < 4; u++) {
            const int bi = bi0 + u * 8;
            ulonglong2* __restrict__ Fr = F2 + bi * (IH / 4);
            const ull rr2 = f2_bcast(rn[u]);
            const ull hv2 = f2_bcast(hn[u]);

            const ulonglong2* __restrict__ xr =
                (const ulonglong2*)(x + ((size_t)bi * Tn + t) * In);
            ulonglong2 xv0 = ldnc2(xr + lane);          // L1 hits
            ulonglong2 xv1 = ldnc2(xr + 32 + lane);
            ulonglong2 Fv0 = Fr[lane], Fv1 = Fr[32 + lane];

            ulonglong2 n0, n1;
            n0.x = f2_fma(g2[0].x, f2_mul(xv0.x, hv2), f2_mul(l2[0].x, f2_mul(Fv0.x, rr2)));
            n0.y = f2_fma(g2[0].y, f2_mul(xv0.y, hv2), f2_mul(l2[0].y, f2_mul(Fv0.y, rr2)));
            n1.x = f2_fma(g2[1].x, f2_mul(xv1.x, hv2), f2_mul(l2[1].x, f2_mul(Fv1.x, rr2)));
            n1.y = f2_fma(g2[1].y, f2_mul(xv1.y, hv2), f2_mul(l2[1].y, f2_mul(Fv1.y, rr2)));
            Fr[lane] = n0;
            Fr[32 + lane] = n1;

            // next-step partials: x-part tw, ss = ss_x + ssh, dx = x(t+1)·tw01
            ull t0x = f2_add(w2[0].x, n0.x), t0y = f2_add(w2[0].y, n0.y);
            ull t1x = f2_add(w2[1].x, n1.x), t1y = f2_add(w2[1].y, n1.y);

            ull ss = f2_mul(t0x, t0x);
            ss = f2_fma(t0y, t0y, ss);
            ss = f2_fma(t1x, t1x, ss);
            ss = f2_fma(t1y, t1y, ss);
            ssp[u] = f2_fold(ss) + ssh[u];

            const ulonglong2* __restrict__ xq =
                (const ulonglong2*)(x + ((size_t)bi * Tn + tn) * In);
            ulonglong2 xa = ldnc2(xq + lane);
            ulonglong2 xb = ldnc2(xq + 32 + lane);
            ull dx = f2_mul(xa.x, t0x);
            dx = f2_fma(xa.y, t0y, dx);
            dx = f2_fma(xb.x, t1x, dx);
            dx = f2_fma(xb.y, t1y, dx);
            dxp[u] = dx;
        }
    }

    // ---- F writeout (warp-private rows) ----
    float* __restrict__ Fout = out + Bn * On + Bn * Hn;
    ulonglong2* __restrict__ Fo2 = (ulonglong2*)Fout;
#pragma unroll
    for (int u = 0; u < 4; u++) {
        const int bb = bi0 + u * 8;
        const int grow = bb * Hn + h;
        const ulonglong2* Fr = F2 + bb * (IH / 4);
#pragma unroll
        for (int k = 0; k < 4; k++) {
            int f4 = k * 32 + lane;
            Fo2[(size_t)grow * (IH / 4) + f4] = Fr[f4];
        }
    }

    // ---- epilogue: needs all blocks' final h ----
    if (blockIdx.x < 64) {
        if (tid == 0) leader_wait((unsigned)(NBLK / NLINES) * (unsigned)Tn);
        __syncthreads();
    }

    if (blockIdx.x < 32) {
        const int b = blockIdx.x;
        for (int i = tid; i < Hn; i += NTHR)
            F_sm[i] = __ldcg(&g_h[0][b * Hn + i]);   // T even -> final h in buf 0
        __syncthreads();
        const float4* hv4 = (const float4*)F_sm;
        for (int o = wid; o < On; o += 8) {
            const float4* wr = (const float4*)(Wout + (size_t)o * Hn);
            float acc = 0.f;
#pragma unroll
            for (int k = 0; k < 2; k++) {
                int j4 = k * 32 + lane;
                float4 w = __ldg(wr + j4);
                float4 hv = hv4[j4];
                acc += w.x * hv.x + w.y * hv.y + w.z * hv.z + w.w * hv.w;
            }
            acc = warp_sum(acc);
            if (lane == 0) out[b * On + o] = acc + __ldg(bout + o);
        }
    } else if (blockIdx.x < 64) {
        const int b = blockIdx.x - 32;
        for (int i = tid; i < Hn; i += NTHR)
            out[Bn * On + b * Hn + i] = __ldcg(&g_h[0][b * Hn + i]);
    }
}

// ---------------------------------------------------------------------------
extern "C" void kernel_launch(void* const* d_in, const int* in_sizes, int n_in,
                              void* d_out, int out_size)
{
    const float* sentence = (const float*)d_in[0];
    const float* Wl   = (const float*)d_in[1];
    const float* Wg   = (const float*)d_in[2];
    const float* W    = (const float*)d_in[3];
    const float* bias = (const float*)d_in[4];
    const float* Wout = (const float*)d_in[5];
    const float* bout = (const float*)d_in[6];
    float* out = (float*)d_out;

    const int smem = 32 * IH * sizeof(float);  // 65536
    cudaFuncSetAttribute(persist_kernel, cudaFuncAttributeMaxDynamicSharedMemorySize, smem);

    init_kernel<<<32, 256>>>();
    persist_kernel<<<NBLK, NTHR, smem>>>(sentence, Wl, Wg, W, bias, Wout, bout, out);
}

// round 15
// speedup vs baseline: 1.7083x; 1.7050x over previous
#include <cuda_runtime.h>

#define Bn 32
#define Tn 128
#define In 256
#define Hn 256
#define IH 512
#define On 128
#define NBLK 256      // persistent blocks; 64 KB smem, <=128 regs => 2 blocks/SM
#define NTHR 256      // 8 warps

typedef unsigned long long ull;

__device__ float g_h[2][Bn * Hn];   // ping-pong hidden state
__device__ unsigned g_bar;          // monotonic grid-barrier counter (1 inc/block/step)

// ---------------------------------------------------------------------------
__global__ void init_kernel()
{
    int i = blockIdx.x * blockDim.x + threadIdx.x;
    if (i == 0) g_bar = 0u;
    for (int k = i; k < Bn * Hn; k += gridDim.x * blockDim.x) g_h[0][k] = 0.f;
}

// ---------------------------------------------------------------------------
__device__ __forceinline__ float warp_sum(float v)
{
#pragma unroll
    for (int o = 16; o > 0; o >>= 1) v += __shfl_xor_sync(0xffffffffu, v, o);
    return v;
}
__device__ __forceinline__ float tanh_fast(float v)
{
    float r; asm("tanh.approx.f32 %0, %1;" : "=f"(r) : "f"(v)); return r;
}
__device__ __forceinline__ unsigned ld_acquire(const unsigned* p)
{
    unsigned v;
    asm volatile("ld.acquire.gpu.global.u32 %0, [%1];" : "=r"(v) : "l"(p) : "memory");
    return v;
}
__device__ __forceinline__ void red_release(unsigned* p)
{
    asm volatile("red.release.gpu.global.add.u32 [%0], 1;" :: "l"(p) : "memory");
}
__device__ __forceinline__ unsigned atom_inc_cta_shared(unsigned* p)
{
    unsigned old;
    unsigned addr = (unsigned)__cvta_generic_to_shared(p);
    asm volatile("atom.acq_rel.cta.shared.add.u32 %0, [%1], 1;"
                 : "=r"(old) : "r"(addr) : "memory");
    return old;
}
// ---- packed f32x2 primitives ----
__device__ __forceinline__ ull f2_add(ull a, ull b)
{ ull d; asm("add.rn.f32x2 %0, %1, %2;" : "=l"(d) : "l"(a), "l"(b)); return d; }
__device__ __forceinline__ ull f2_mul(ull a, ull b)
{ ull d; asm("mul.rn.f32x2 %0, %1, %2;" : "=l"(d) : "l"(a), "l"(b)); return d; }
__device__ __forceinline__ ull f2_fma(ull a, ull b, ull c)
{ ull d; asm("fma.rn.f32x2 %0, %1, %2, %3;" : "=l"(d) : "l"(a), "l"(b), "l"(c)); return d; }
__device__ __forceinline__ ull f2_bcast(float v)
{ ull d; asm("mov.b64 %0, {%1, %1};" : "=l"(d) : "f"(v)); return d; }
__device__ __forceinline__ float f2_fold(ull v)
{ float lo, hi; asm("mov.b64 {%0, %1}, %2;" : "=f"(lo), "=f"(hi) : "l"(v)); return lo + hi; }
__device__ __forceinline__ ulonglong2 ldnc2(const ulonglong2* p)
{ ulonglong2 v; asm("ld.global.nc.v2.u64 {%0,%1}, [%2];" : "=l"(v.x), "=l"(v.y) : "l"(p)); return v; }
__device__ __forceinline__ ulonglong2 ldcg2(const ulonglong2* p)
{ ulonglong2 v; asm volatile("ld.global.cg.v2.u64 {%0,%1}, [%2];" : "=l"(v.x), "=l"(v.y) : "l"(p)); return v; }

// ---------------------------------------------------------------------------
// Persistent kernel, 2 blocks/SM (R12 structure: fused h-part writeback; the
// proven sync shape: leader single-acquire poll -> bar.sync -> smem-atom
// arrive -> ONE red.release per block on ONE counter line).
// Block owns h-row bid x 32 batches; F slice (32 rows x 512 = 64 KB) in smem.
// Warp w handles batches w + {0,8,16,24}; lane slice: 16B unit k*32+lane.
// ---------------------------------------------------------------------------
__global__ __launch_bounds__(NTHR, 2) void persist_kernel(
    const float* __restrict__ x,
    const float* __restrict__ Wl,
    const float* __restrict__ Wg,
    const float* __restrict__ W,
    const float* __restrict__ bias,
    const float* __restrict__ Wout,
    const float* __restrict__ bout,
    float* __restrict__ out)
{
    extern __shared__ float F_sm[];                    // 64 KB
    ulonglong2* __restrict__ F2 = (ulonglong2*)F_sm;   // [32][128] 16B units
    __shared__ unsigned s_cnt;

    const int tid  = threadIdx.x;
    const int wid  = tid >> 5, lane = tid & 31;
    const int bi0  = wid;                      // 0..7
    const int h    = blockIdx.x;

    if (tid == 0) s_cnt = 0u;

    // Pin this block's weight-row slices (pair domain).
    ulonglong2 w2[4], l2[4], g2[4];
    {
        const ulonglong2* Wp = (const ulonglong2*)(W  + (size_t)h * IH);
        const ulonglong2* Lp = (const ulonglong2*)(Wl + (size_t)h * IH);
        const ulonglong2* Gp = (const ulonglong2*)(Wg + (size_t)h * IH);
#pragma unroll
        for (int k = 0; k < 4; k++) {
            int f4 = k * 32 + lane;
            w2[k] = ldnc2(Wp + f4);
            l2[k] = ldnc2(Lp + f4);
            g2[k] = ldnc2(Gp + f4);
        }
    }
    const float bia = __ldg(bias + h);

    // Zero this warp's F rows.
    {
        ulonglong2 z; z.x = 0ull; z.y = 0ull;
#pragma unroll
        for (int u = 0; u < 4; u++) {
            ulonglong2* Fr = F2 + (bi0 + u * 8) * (IH / 4);
#pragma unroll
            for (int k = 0; k < 4; k++) Fr[k * 32 + lane] = z;
        }
    }

    // Bootstrap partials for t=0 (F=0 => tw=W).
    float ssp[4], rn[4], hn[4];
    ull dxp[4], ssh[4];
    {
        ull sw = f2_mul(w2[0].x, w2[0].x);
        sw = f2_fma(w2[0].y, w2[0].y, sw);
        sw = f2_fma(w2[1].x, w2[1].x, sw);
        sw = f2_fma(w2[1].y, w2[1].y, sw);
        sw = f2_fma(w2[2].x, w2[2].x, sw);
        sw = f2_fma(w2[2].y, w2[2].y, sw);
        sw = f2_fma(w2[3].x, w2[3].x, sw);
        sw = f2_fma(w2[3].y, w2[3].y, sw);
        const float ssw = f2_fold(sw);
#pragma unroll
        for (int u = 0; u < 4; u++) {
            const int bi = bi0 + u * 8;
            const ulonglong2* xr = (const ulonglong2*)(x + (size_t)bi * Tn * In);
            ulonglong2 xv0 = ldnc2(xr + lane);
            ulonglong2 xv1 = ldnc2(xr + 32 + lane);
            ull a = f2_mul(xv0.x, w2[0].x);
            a = f2_fma(xv0.y, w2[0].y, a);
            a = f2_fma(xv1.x, w2[1].x, a);
            a = f2_fma(xv1.y, w2[1].y, a);
            ssp[u] = ssw;
            dxp[u] = a;
        }
    }

    for (int t = 0; t < Tn; t++) {
        const ulonglong2* __restrict__ hin = (const ulonglong2*)g_h[t & 1];
        float* __restrict__ hout = g_h[(t & 1) ^ 1];
        const int tn = (t + 1 < Tn) ? t + 1 : t;

        // ss reduce + rsqrt (off critical path; 4 interleaved chains).
#pragma unroll
        for (int o = 16; o > 0; o >>= 1) {
            ssp[0] += __shfl_xor_sync(0xffffffffu, ssp[0], o);
            ssp[1] += __shfl_xor_sync(0xffffffffu, ssp[1], o);
            ssp[2] += __shfl_xor_sync(0xffffffffu, ssp[2], o);
            ssp[3] += __shfl_xor_sync(0xffffffffu, ssp[3], o);
        }
#pragma unroll
        for (int u = 0; u < 4; u++) rn[u] = rsqrtf(ssp[u]);

        // ---------- wait: h(t-1) published by all blocks ----------
        if (tid == 0) {
            const unsigned target = (unsigned)NBLK * (unsigned)t;
            while (ld_acquire(&g_bar) < target) __nanosleep(24);
        }
        __syncthreads();

        // ---------- B1: per batch, dot -> publish h -> fused h-part writeback ----------
        ulonglong2 ha[4], hb[4];
#pragma unroll
        for (int u = 0; u < 4; u++) {          // 8 LDGs up front (MLP)
            const int bi = bi0 + u * 8;
            ha[u] = ldcg2(hin + bi * (Hn / 16) * 4 + lane);
            hb[u] = ldcg2(hin + bi * (Hn / 16) * 4 + 32 + lane);
        }
#pragma unroll
        for (int u = 0; u < 4; u++) {
            const int bi = bi0 + u * 8;
            ulonglong2* __restrict__ Fr = F2 + bi * (IH / 4);
            ulonglong2 Fv2 = Fr[64 + lane], Fv3 = Fr[96 + lane];
            ull t2x = f2_add(w2[2].x, Fv2.x), t2y = f2_add(w2[2].y, Fv2.y);
            ull t3x = f2_add(w2[3].x, Fv3.x), t3y = f2_add(w2[3].y, Fv3.y);
            ull acc = dxp[u];
            acc = f2_fma(ha[u].x, t2x, acc);
            acc = f2_fma(ha[u].y, t2y, acc);
            acc = f2_fma(hb[u].x, t3x, acc);
            acc = f2_fma(hb[u].y, t3y, acc);
            float tot = warp_sum(f2_fold(acc));
            const float hv = tanh_fast(tot + bia) * rn[u];
            hn[u] = hv;
            if (lane == 0) hout[bi * Hn + h] = hv;

            // fused h-part writeback (Fv2/3, ha/hb still live — no reload)
            const ull rr2 = f2_bcast(rn[u]);
            const ull hv2 = f2_bcast(hv);
            ulonglong2 n2, n3;
            n2.x = f2_fma(g2[2].x, f2_mul(ha[u].x, hv2), f2_mul(l2[2].x, f2_mul(Fv2.x, rr2)));
            n2.y = f2_fma(g2[2].y, f2_mul(ha[u].y, hv2), f2_mul(l2[2].y, f2_mul(Fv2.y, rr2)));
            n3.x = f2_fma(g2[3].x, f2_mul(hb[u].x, hv2), f2_mul(l2[3].x, f2_mul(Fv3.x, rr2)));
            n3.y = f2_fma(g2[3].y, f2_mul(hb[u].y, hv2), f2_mul(l2[3].y, f2_mul(Fv3.y, rr2)));
            Fr[64 + lane] = n2;
            Fr[96 + lane] = n3;

            // h-part contribution to next-step ss, kept PACKED (folded in B2)
            ull u2x = f2_add(w2[2].x, n2.x), u2y = f2_add(w2[2].y, n2.y);
            ull u3x = f2_add(w2[3].x, n3.x), u3y = f2_add(w2[3].y, n3.y);
            ull sh = f2_mul(u2x, u2x);
            sh = f2_fma(u2y, u2y, sh);
            sh = f2_fma(u3x, u3x, sh);
            sh = f2_fma(u3y, u3y, sh);
            ssh[u] = sh;
        }

        // ---------- arrive (smem acq_rel -> 1 global red per block) ----------
        if (lane == 0) {
            unsigned old = atom_inc_cta_shared(&s_cnt);
            if ((old & 7u) == 7u) red_release(&g_bar);
        }

        // ---------- B2 (off critical path): x-part writeback + partials ----------
#pragma unroll
        for (int u = 0; u < 4; u++) {
            const int bi = bi0 + u * 8;
            ulonglong2* __restrict__ Fr = F2 + bi * (IH / 4);
            const ull rr2 = f2_bcast(rn[u]);
            const ull hv2 = f2_bcast(hn[u]);

            const ulonglong2* __restrict__ xr =
                (const ulonglong2*)(x + ((size_t)bi * Tn + t) * In);
            ulonglong2 xv0 = ldnc2(xr + lane);          // L1 hits
            ulonglong2 xv1 = ldnc2(xr + 32 + lane);
            ulonglong2 Fv0 = Fr[lane], Fv1 = Fr[32 + lane];

            ulonglong2 n0, n1;
            n0.x = f2_fma(g2[0].x, f2_mul(xv0.x, hv2), f2_mul(l2[0].x, f2_mul(Fv0.x, rr2)));
            n0.y = f2_fma(g2[0].y, f2_mul(xv0.y, hv2), f2_mul(l2[0].y, f2_mul(Fv0.y, rr2)));
            n1.x = f2_fma(g2[1].x, f2_mul(xv1.x, hv2), f2_mul(l2[1].x, f2_mul(Fv1.x, rr2)));
            n1.y = f2_fma(g2[1].y, f2_mul(xv1.y, hv2), f2_mul(l2[1].y, f2_mul(Fv1.y, rr2)));
            Fr[lane] = n0;
            Fr[32 + lane] = n1;

            // next-step partials: ss = fold(ss_x + ssh_packed), dx = x(t+1)·tw01
            ull t0x = f2_add(w2[0].x, n0.x), t0y = f2_add(w2[0].y, n0.y);
            ull t1x = f2_add(w2[1].x, n1.x), t1y = f2_add(w2[1].y, n1.y);

            ull ss = f2_fma(t0x, t0x, ssh[u]);
            ss = f2_fma(t0y, t0y, ss);
            ss = f2_fma(t1x, t1x, ss);
            ss = f2_fma(t1y, t1y, ss);
            ssp[u] = f2_fold(ss);

            const ulonglong2* __restrict__ xq =
                (const ulonglong2*)(x + ((size_t)bi * Tn + tn) * In);
            ulonglong2 xa = ldnc2(xq + lane);
            ulonglong2 xb = ldnc2(xq + 32 + lane);
            ull dx = f2_mul(xa.x, t0x);
            dx = f2_fma(xa.y, t0y, dx);
            dx = f2_fma(xb.x, t1x, dx);
            dx = f2_fma(xb.y, t1y, dx);
            dxp[u] = dx;
        }
    }

    // ---- F writeout (warp-private rows) ----
    float* __restrict__ Fout = out + Bn * On + Bn * Hn;
    ulonglong2* __restrict__ Fo2 = (ulonglong2*)Fout;
#pragma unroll
    for (int u = 0; u < 4; u++) {
        const int bb = bi0 + u * 8;
        const int grow = bb * Hn + h;
        const ulonglong2* Fr = F2 + bb * (IH / 4);
#pragma unroll
        for (int k = 0; k < 4; k++) {
            int f4 = k * 32 + lane;
            Fo2[(size_t)grow * (IH / 4) + f4] = Fr[f4];
        }
    }

    // ---- epilogue: needs all blocks' final h ----
    if (blockIdx.x < 64) {
        if (tid == 0) {
            const unsigned target = (unsigned)NBLK * (unsigned)Tn;
            while (ld_acquire(&g_bar) < target) __nanosleep(24);
        }
        __syncthreads();
    }

    if (blockIdx.x < 32) {
        const int b = blockIdx.x;
        for (int i = tid; i < Hn; i += NTHR)
            F_sm[i] = __ldcg(&g_h[0][b * Hn + i]);   // T even -> final h in buf 0
        __syncthreads();
        const float4* hv4 = (const float4*)F_sm;
        for (int o = wid; o < On; o += 8) {
            const float4* wr = (const float4*)(Wout + (size_t)o * Hn);
            float acc = 0.f;
#pragma unroll
            for (int k = 0; k < 2; k++) {
                int j4 = k * 32 + lane;
                float4 w = __ldg(wr + j4);
                float4 hv = hv4[j4];
                acc += w.x * hv.x + w.y * hv.y + w.z * hv.z + w.w * hv.w;
            }
            acc = warp_sum(acc);
            if (lane == 0) out[b * On + o] = acc + __ldg(bout + o);
        }
    } else if (blockIdx.x < 64) {
        const int b = blockIdx.x - 32;
        for (int i = tid; i < Hn; i += NTHR)
            out[Bn * On + b * Hn + i] = __ldcg(&g_h[0][b * Hn + i]);
    }
}

// ---------------------------------------------------------------------------
extern "C" void kernel_launch(void* const* d_in, const int* in_sizes, int n_in,
                              void* d_out, int out_size)
{
    const float* sentence = (const float*)d_in[0];
    const float* Wl   = (const float*)d_in[1];
    const float* Wg   = (const float*)d_in[2];
    const float* W    = (const float*)d_in[3];
    const float* bias = (const float*)d_in[4];
    const float* Wout = (const float*)d_in[5];
    const float* bout = (const float*)d_in[6];
    float* out = (float*)d_out;

    const int smem = 32 * IH * sizeof(float);  // 65536
    cudaFuncSetAttribute(persist_kernel, cudaFuncAttributeMaxDynamicSharedMemorySize, smem);

    init_kernel<<<32, 256>>>();
    persist_kernel<<<NBLK, NTHR, smem>>>(sentence, Wl, Wg, W, bias, Wout, bout, out);
}

// round 16
// speedup vs baseline: 1.7526x; 1.0259x over previous
#include <cuda_runtime.h>

#define Bn 32
#define Tn 128
#define In 256
#define Hn 256
#define IH 512
#define On 128
#define NBLK 256      // persistent blocks; 64 KB smem, <=128 regs => 2 blocks/SM
#define NTHR 256      // 8 warps

typedef unsigned long long ull;

__device__ float g_h[2][Bn * Hn];   // ping-pong hidden state
__device__ unsigned g_bar;          // monotonic grid-barrier counter (1 inc/block/step)

// ---------------------------------------------------------------------------
__global__ void init_kernel()
{
    int i = blockIdx.x * blockDim.x + threadIdx.x;
    if (i == 0) g_bar = 0u;
    for (int k = i; k < Bn * Hn; k += gridDim.x * blockDim.x) g_h[0][k] = 0.f;
}

// ---------------------------------------------------------------------------
__device__ __forceinline__ float tanh_fast(float v)
{
    float r; asm("tanh.approx.f32 %0, %1;" : "=f"(r) : "f"(v)); return r;
}
__device__ __forceinline__ unsigned ld_acquire(const unsigned* p)
{
    unsigned v;
    asm volatile("ld.acquire.gpu.global.u32 %0, [%1];" : "=r"(v) : "l"(p) : "memory");
    return v;
}
__device__ __forceinline__ void red_release(unsigned* p)
{
    asm volatile("red.release.gpu.global.add.u32 [%0], 1;" :: "l"(p) : "memory");
}
__device__ __forceinline__ unsigned atom_inc_cta_shared(unsigned* p)
{
    unsigned old;
    unsigned addr = (unsigned)__cvta_generic_to_shared(p);
    asm volatile("atom.acq_rel.cta.shared.add.u32 %0, [%1], 1;"
                 : "=r"(old) : "r"(addr) : "memory");
    return old;
}
// ---- packed f32x2 primitives ----
__device__ __forceinline__ ull f2_add(ull a, ull b)
{ ull d; asm("add.rn.f32x2 %0, %1, %2;" : "=l"(d) : "l"(a), "l"(b)); return d; }
__device__ __forceinline__ ull f2_mul(ull a, ull b)
{ ull d; asm("mul.rn.f32x2 %0, %1, %2;" : "=l"(d) : "l"(a), "l"(b)); return d; }
__device__ __forceinline__ ull f2_fma(ull a, ull b, ull c)
{ ull d; asm("fma.rn.f32x2 %0, %1, %2, %3;" : "=l"(d) : "l"(a), "l"(b), "l"(c)); return d; }
__device__ __forceinline__ ull f2_bcast(float v)
{ ull d; asm("mov.b64 %0, {%1, %1};" : "=l"(d) : "f"(v)); return d; }
__device__ __forceinline__ float f2_fold(ull v)
{ float lo, hi; asm("mov.b64 {%0, %1}, %2;" : "=f"(lo), "=f"(hi) : "l"(v)); return lo + hi; }
__device__ __forceinline__ ulonglong2 ldnc2(const ulonglong2* p)
{ ulonglong2 v; asm("ld.global.nc.v2.u64 {%0,%1}, [%2];" : "=l"(v.x), "=l"(v.y) : "l"(p)); return v; }
__device__ __forceinline__ ulonglong2 ldcg2(const ulonglong2* p)
{ ulonglong2 v; asm volatile("ld.global.cg.v2.u64 {%0,%1}, [%2];" : "=l"(v.x), "=l"(v.y) : "l"(p)); return v; }

// ---------------------------------------------------------------------------
// Persistent kernel, 2 blocks/SM. Block owns h-row bid x 32 batches; F slice
// (32 rows x 512 = 64 KB) in smem. Warp w handles batches w + {0,8,16,24}.
// Lane slice: 16B unit k*32+lane.
//
// Step (critical span minimized):
//   [ss reduce -> rn | leader 1-acquire poll + bar.sync |
//    B1a: 8 h-LDGs, 4x acc (only acc kept) |
//    B1b: 4-way INTERLEAVED butterfly (~150cyc, was ~520 serial) |
//    B1c: tanh -> 4 STG h | ARRIVE |
//    B1d (post-arrive): h-part writeback (re-LDS Fv2/3) + packed ssh |
//    B2: x-part writeback + next-step ss/dx partials]
// Nothing after ARRIVE reads hin (ha/hb register-resident) -> ping-pong safe.
// ---------------------------------------------------------------------------
__global__ __launch_bounds__(NTHR, 2) void persist_kernel(
    const float* __restrict__ x,
    const float* __restrict__ Wl,
    const float* __restrict__ Wg,
    const float* __restrict__ W,
    const float* __restrict__ bias,
    const float* __restrict__ Wout,
    const float* __restrict__ bout,
    float* __restrict__ out)
{
    extern __shared__ float F_sm[];                    // 64 KB
    ulonglong2* __restrict__ F2 = (ulonglong2*)F_sm;   // [32][128] 16B units
    __shared__ unsigned s_cnt;

    const int tid  = threadIdx.x;
    const int wid  = tid >> 5, lane = tid & 31;
    const int bi0  = wid;                      // 0..7
    const int h    = blockIdx.x;

    if (tid == 0) s_cnt = 0u;

    // Pin this block's weight-row slices (pair domain).
    ulonglong2 w2[4], l2[4], g2[4];
    {
        const ulonglong2* Wp = (const ulonglong2*)(W  + (size_t)h * IH);
        const ulonglong2* Lp = (const ulonglong2*)(Wl + (size_t)h * IH);
        const ulonglong2* Gp = (const ulonglong2*)(Wg + (size_t)h * IH);
#pragma unroll
        for (int k = 0; k < 4; k++) {
            int f4 = k * 32 + lane;
            w2[k] = ldnc2(Wp + f4);
            l2[k] = ldnc2(Lp + f4);
            g2[k] = ldnc2(Gp + f4);
        }
    }
    const float bia = __ldg(bias + h);

    // Zero this warp's F rows.
    {
        ulonglong2 z; z.x = 0ull; z.y = 0ull;
#pragma unroll
        for (int u = 0; u < 4; u++) {
            ulonglong2* Fr = F2 + (bi0 + u * 8) * (IH / 4);
#pragma unroll
            for (int k = 0; k < 4; k++) Fr[k * 32 + lane] = z;
        }
    }

    // Bootstrap partials for t=0 (F=0 => tw=W).
    float ssp[4], rn[4], hn[4];
    ull dxp[4], ssh[4];
    {
        ull sw = f2_mul(w2[0].x, w2[0].x);
        sw = f2_fma(w2[0].y, w2[0].y, sw);
        sw = f2_fma(w2[1].x, w2[1].x, sw);
        sw = f2_fma(w2[1].y, w2[1].y, sw);
        sw = f2_fma(w2[2].x, w2[2].x, sw);
        sw = f2_fma(w2[2].y, w2[2].y, sw);
        sw = f2_fma(w2[3].x, w2[3].x, sw);
        sw = f2_fma(w2[3].y, w2[3].y, sw);
        const float ssw = f2_fold(sw);
#pragma unroll
        for (int u = 0; u < 4; u++) {
            const int bi = bi0 + u * 8;
            const ulonglong2* xr = (const ulonglong2*)(x + (size_t)bi * Tn * In);
            ulonglong2 xv0 = ldnc2(xr + lane);
            ulonglong2 xv1 = ldnc2(xr + 32 + lane);
            ull a = f2_mul(xv0.x, w2[0].x);
            a = f2_fma(xv0.y, w2[0].y, a);
            a = f2_fma(xv1.x, w2[1].x, a);
            a = f2_fma(xv1.y, w2[1].y, a);
            ssp[u] = ssw;
            dxp[u] = a;
        }
    }

    for (int t = 0; t < Tn; t++) {
        const ulonglong2* __restrict__ hin = (const ulonglong2*)g_h[t & 1];
        float* __restrict__ hout = g_h[(t & 1) ^ 1];
        const int tn = (t + 1 < Tn) ? t + 1 : t;

        // ss reduce + rsqrt (off critical path; 4 interleaved chains).
#pragma unroll
        for (int o = 16; o > 0; o >>= 1) {
            ssp[0] += __shfl_xor_sync(0xffffffffu, ssp[0], o);
            ssp[1] += __shfl_xor_sync(0xffffffffu, ssp[1], o);
            ssp[2] += __shfl_xor_sync(0xffffffffu, ssp[2], o);
            ssp[3] += __shfl_xor_sync(0xffffffffu, ssp[3], o);
        }
#pragma unroll
        for (int u = 0; u < 4; u++) rn[u] = rsqrtf(ssp[u]);

        // ---------- wait: h(t-1) published by all blocks ----------
        if (tid == 0) {
            const unsigned target = (unsigned)NBLK * (unsigned)t;
            while (ld_acquire(&g_bar) < target) __nanosleep(24);
        }
        __syncthreads();

        // ---------- B1a: h loads + per-lane accs (only acc kept) ----------
        ulonglong2 ha[4], hb[4];
#pragma unroll
        for (int u = 0; u < 4; u++) {          // 8 LDGs up front (MLP)
            const int bi = bi0 + u * 8;
            ha[u] = ldcg2(hin + bi * (Hn / 16) * 4 + lane);
            hb[u] = ldcg2(hin + bi * (Hn / 16) * 4 + 32 + lane);
        }
        float accf[4];
#pragma unroll
        for (int u = 0; u < 4; u++) {
            const int bi = bi0 + u * 8;
            const ulonglong2* __restrict__ Fr = F2 + bi * (IH / 4);
            ulonglong2 Fv2 = Fr[64 + lane], Fv3 = Fr[96 + lane];
            ull t2x = f2_add(w2[2].x, Fv2.x), t2y = f2_add(w2[2].y, Fv2.y);
            ull t3x = f2_add(w2[3].x, Fv3.x), t3y = f2_add(w2[3].y, Fv3.y);
            ull acc = dxp[u];
            acc = f2_fma(ha[u].x, t2x, acc);
            acc = f2_fma(ha[u].y, t2y, acc);
            acc = f2_fma(hb[u].x, t3x, acc);
            acc = f2_fma(hb[u].y, t3y, acc);
            accf[u] = f2_fold(acc);
        }

        // ---------- B1b: 4-way interleaved butterfly ----------
#pragma unroll
        for (int o = 16; o > 0; o >>= 1) {
            accf[0] += __shfl_xor_sync(0xffffffffu, accf[0], o);
            accf[1] += __shfl_xor_sync(0xffffffffu, accf[1], o);
            accf[2] += __shfl_xor_sync(0xffffffffu, accf[2], o);
            accf[3] += __shfl_xor_sync(0xffffffffu, accf[3], o);
        }

        // ---------- B1c: tanh -> publish h ----------
#pragma unroll
        for (int u = 0; u < 4; u++) {
            const int bi = bi0 + u * 8;
            const float hv = tanh_fast(accf[u] + bia) * rn[u];
            hn[u] = hv;
            if (lane == 0) hout[bi * Hn + h] = hv;
        }

        // ---------- ARRIVE (smem acq_rel -> 1 global red per block) ----------
        if (lane == 0) {
            unsigned old = atom_inc_cta_shared(&s_cnt);
            if ((old & 7u) == 7u) red_release(&g_bar);
        }

        // ---------- B1d (post-arrive): h-part writeback + packed ssh ----------
#pragma unroll
        for (int u = 0; u < 4; u++) {
            const int bi = bi0 + u * 8;
            ulonglong2* __restrict__ Fr = F2 + bi * (IH / 4);
            ulonglong2 Fv2 = Fr[64 + lane], Fv3 = Fr[96 + lane];
            const ull rr2 = f2_bcast(rn[u]);
            const ull hv2 = f2_bcast(hn[u]);
            ulonglong2 n2, n3;
            n2.x = f2_fma(g2[2].x, f2_mul(ha[u].x, hv2), f2_mul(l2[2].x, f2_mul(Fv2.x, rr2)));
            n2.y = f2_fma(g2[2].y, f2_mul(ha[u].y, hv2), f2_mul(l2[2].y, f2_mul(Fv2.y, rr2)));
            n3.x = f2_fma(g2[3].x, f2_mul(hb[u].x, hv2), f2_mul(l2[3].x, f2_mul(Fv3.x, rr2)));
            n3.y = f2_fma(g2[3].y, f2_mul(hb[u].y, hv2), f2_mul(l2[3].y, f2_mul(Fv3.y, rr2)));
            Fr[64 + lane] = n2;
            Fr[96 + lane] = n3;

            // h-part contribution to next-step ss, kept PACKED (folded in B2)
            ull u2x = f2_add(w2[2].x, n2.x), u2y = f2_add(w2[2].y, n2.y);
            ull u3x = f2_add(w2[3].x, n3.x), u3y = f2_add(w2[3].y, n3.y);
            ull sh = f2_mul(u2x, u2x);
            sh = f2_fma(u2y, u2y, sh);
            sh = f2_fma(u3x, u3x, sh);
            sh = f2_fma(u3y, u3y, sh);
            ssh[u] = sh;
        }

        // ---------- B2 (off critical path): x-part writeback + partials ----------
#pragma unroll
        for (int u = 0; u < 4; u++) {
            const int bi = bi0 + u * 8;
            ulonglong2* __restrict__ Fr = F2 + bi * (IH / 4);
            const ull rr2 = f2_bcast(rn[u]);
            const ull hv2 = f2_bcast(hn[u]);

            const ulonglong2* __restrict__ xr =
                (const ulonglong2*)(x + ((size_t)bi * Tn + t) * In);
            ulonglong2 xv0 = ldnc2(xr + lane);          // L1 hits
            ulonglong2 xv1 = ldnc2(xr + 32 + lane);
            ulonglong2 Fv0 = Fr[lane], Fv1 = Fr[32 + lane];

            ulonglong2 n0, n1;
            n0.x = f2_fma(g2[0].x, f2_mul(xv0.x, hv2), f2_mul(l2[0].x, f2_mul(Fv0.x, rr2)));
            n0.y = f2_fma(g2[0].y, f2_mul(xv0.y, hv2), f2_mul(l2[0].y, f2_mul(Fv0.y, rr2)));
            n1.x = f2_fma(g2[1].x, f2_mul(xv1.x, hv2), f2_mul(l2[1].x, f2_mul(Fv1.x, rr2)));
            n1.y = f2_fma(g2[1].y, f2_mul(xv1.y, hv2), f2_mul(l2[1].y, f2_mul(Fv1.y, rr2)));
            Fr[lane] = n0;
            Fr[32 + lane] = n1;

            // next-step partials: ss = fold(ss_x + ssh_packed), dx = x(t+1)·tw01
            ull t0x = f2_add(w2[0].x, n0.x), t0y = f2_add(w2[0].y, n0.y);
            ull t1x = f2_add(w2[1].x, n1.x), t1y = f2_add(w2[1].y, n1.y);

            ull ss = f2_fma(t0x, t0x, ssh[u]);
            ss = f2_fma(t0y, t0y, ss);
            ss = f2_fma(t1x, t1x, ss);
            ss = f2_fma(t1y, t1y, ss);
            ssp[u] = f2_fold(ss);

            const ulonglong2* __restrict__ xq =
                (const ulonglong2*)(x + ((size_t)bi * Tn + tn) * In);
            ulonglong2 xa = ldnc2(xq + lane);
            ulonglong2 xb = ldnc2(xq + 32 + lane);
            ull dx = f2_mul(xa.x, t0x);
            dx = f2_fma(xa.y, t0y, dx);
            dx = f2_fma(xb.x, t1x, dx);
            dx = f2_fma(xb.y, t1y, dx);
            dxp[u] = dx;
        }
    }

    // ---- F writeout (warp-private rows) ----
    float* __restrict__ Fout = out + Bn * On + Bn * Hn;
    ulonglong2* __restrict__ Fo2 = (ulonglong2*)Fout;
#pragma unroll
    for (int u = 0; u < 4; u++) {
        const int bb = bi0 + u * 8;
        const int grow = bb * Hn + h;
        const ulonglong2* Fr = F2 + bb * (IH / 4);
#pragma unroll
        for (int k = 0; k < 4; k++) {
            int f4 = k * 32 + lane;
            Fo2[(size_t)grow * (IH / 4) + f4] = Fr[f4];
        }
    }

    // ---- epilogue: needs all blocks' final h ----
    if (blockIdx.x < 64) {
        if (tid == 0) {
            const unsigned target = (unsigned)NBLK * (unsigned)Tn;
            while (ld_acquire(&g_bar) < target) __nanosleep(24);
        }
        __syncthreads();
    }

    if (blockIdx.x < 32) {
        const int b = blockIdx.x;
        for (int i = tid; i < Hn; i += NTHR)
            F_sm[i] = __ldcg(&g_h[0][b * Hn + i]);   // T even -> final h in buf 0
        __syncthreads();
        const float4* hv4 = (const float4*)F_sm;
        for (int o = wid; o < On; o += 8) {
            const float4* wr = (const float4*)(Wout + (size_t)o * Hn);
            float acc = 0.f;
#pragma unroll
            for (int k = 0; k < 2; k++) {
                int j4 = k * 32 + lane;
                float4 w = __ldg(wr + j4);
                float4 hv = hv4[j4];
                acc += w.x * hv.x + w.y * hv.y + w.z * hv.z + w.w * hv.w;
            }
#pragma unroll
            for (int off = 16; off > 0; off >>= 1)
                acc += __shfl_xor_sync(0xffffffffu, acc, off);
            if (lane == 0) out[b * On + o] = acc + __ldg(bout + o);
        }
    } else if (blockIdx.x < 64) {
        const int b = blockIdx.x - 32;
        for (int i = tid; i < Hn; i += NTHR)
            out[Bn * On + b * Hn + i] = __ldcg(&g_h[0][b * Hn + i]);
    }
}

// ---------------------------------------------------------------------------
extern "C" void kernel_launch(void* const* d_in, const int* in_sizes, int n_in,
                              void* d_out, int out_size)
{
    const float* sentence = (const float*)d_in[0];
    const float* Wl   = (const float*)d_in[1];
    const float* Wg   = (const float*)d_in[2];
    const float* W    = (const float*)d_in[3];
    const float* bias = (const float*)d_in[4];
    const float* Wout = (const float*)d_in[5];
    const float* bout = (const float*)d_in[6];
    float* out = (float*)d_out;

    const int smem = 32 * IH * sizeof(float);  // 65536
    cudaFuncSetAttribute(persist_kernel, cudaFuncAttributeMaxDynamicSharedMemorySize, smem);

    init_kernel<<<32, 256>>>();
    persist_kernel<<<NBLK, NTHR, smem>>>(sentence, Wl, Wg, W, bias, Wout, bout, out);
}